// round 1
// baseline (speedup 1.0000x reference)
#include <cuda_runtime.h>

// FilterTransform: two cascaded DF2T biquads over time for x[4096,16000] and
// n[4096,16000]. Filter 1 fixed high-pass (b=-2,1 / a=-1.99599,0.996),
// filter 2 uses scalar coeffs b_*[0], b_*[1] / a_*[0], a_*[1].
// Output: [x_filt ; n_filt] row-major, 2*4096*16000 floats.

static constexpr int T_LEN  = 16000;
static constexpr int B_ROWS = 4096;
static constexpr int NF4    = T_LEN / 4;    // 4000 float4 per row
static constexpr int BATCH  = 16;           // float4 per register batch (64 floats)
static constexpr int NBATCH = NF4 / BATCH;  // 250

__global__ __launch_bounds__(32, 1)
void biquad_cascade_kernel(const float* __restrict__ x,
                           const float* __restrict__ n,
                           const float* __restrict__ a_x,
                           const float* __restrict__ b_x,
                           const float* __restrict__ a_n,
                           const float* __restrict__ b_n,
                           float* __restrict__ out)
{
    const int r = blockIdx.x * 32 + threadIdx.x;   // 0..8191

    const float* in;
    float a0, a1, b0, b1;
    if (r < B_ROWS) {
        in = x + (size_t)r * T_LEN;
        a0 = a_x[0]; a1 = a_x[1]; b0 = b_x[0]; b1 = b_x[1];
    } else {
        in = n + (size_t)(r - B_ROWS) * T_LEN;
        a0 = a_n[0]; a1 = a_n[1]; b0 = b_n[0]; b1 = b_n[1];
    }
    float* o = out + (size_t)r * T_LEN;

    // High-pass biquad constants
    const float A0 = -1.99599f;   // a0_hp
    const float A1 =  0.996f;     // a1_hp
    // b0_hp = -2, b1_hp = 1 (folded into fmas below)

    // DF2T states: (m0,m1) for HP stage, (p0,p1) for random stage
    float m0 = 0.f, m1 = 0.f, p0 = 0.f, p1 = 0.f;

    const float4* in4 = (const float4*)in;
    float4*       o4  = (float4*)o;

    // Double-buffered register batches: 16 back-to-back LDG.128 per batch
    // gives per-thread MLP ~16 to hide DRAM latency at ~1.7 warps/SM.
    float4 buf[2][BATCH];
    #pragma unroll
    for (int j = 0; j < BATCH; j++) buf[0][j] = in4[j];

    for (int bi = 0; bi < NBATCH; bi++) {
        const int cur = bi & 1;
        if (bi + 1 < NBATCH) {
            const float4* src = in4 + (size_t)(bi + 1) * BATCH;
            #pragma unroll
            for (int j = 0; j < BATCH; j++) buf[cur ^ 1][j] = src[j];
        }
        float4* dst = o4 + (size_t)bi * BATCH;
        #pragma unroll
        for (int j = 0; j < BATCH; j++) {
            float4 v = buf[cur][j];
            float xs[4] = {v.x, v.y, v.z, v.w};
            float ys[4];
            #pragma unroll
            for (int k = 0; k < 4; k++) {
                const float xv = xs[k];
                // Stage 1: high-pass. y1 = x + m0
                const float y1 = xv + m0;
                // m0' = m1 + (-2)*x - A0*y1 ; m1' = 1*x - A1*y1
                m0 = fmaf(-A0, y1, fmaf(-2.0f, xv, m1));
                m1 = fmaf(-A1, y1, xv);
                // Stage 2: random coeffs. y2 = y1 + p0
                const float y2 = y1 + p0;
                p0 = fmaf(-a0, y2, fmaf(b0, y1, p1));
                p1 = fmaf(-a1, y2, b1 * y1);
                ys[k] = y2;
            }
            dst[j] = make_float4(ys[0], ys[1], ys[2], ys[3]);
        }
    }
}

extern "C" void kernel_launch(void* const* d_in, const int* in_sizes, int n_in,
                              void* d_out, int out_size)
{
    const float* x   = (const float*)d_in[0];
    const float* n   = (const float*)d_in[1];
    const float* a_x = (const float*)d_in[2];
    const float* b_x = (const float*)d_in[3];
    const float* a_n = (const float*)d_in[4];
    const float* b_n = (const float*)d_in[5];
    float* out = (float*)d_out;

    // 8192 rows, one thread each; 32-thread blocks spread over all SMs.
    biquad_cascade_kernel<<<(2 * B_ROWS) / 32, 32>>>(x, n, a_x, b_x, a_n, b_n, out);
}

// round 2
// speedup vs baseline: 1.3233x; 1.3233x over previous
#include <cuda_runtime.h>

// FilterTransform: two cascaded DF2T biquads over time for x[4096,16000] and
// n[4096,16000]. Stage 1 fixed high-pass (b=-2,1 / a=-1.99599,0.996),
// stage 2 uses scalar coeffs b_*[0], b_*[1] / a_*[0], a_*[1].
// Output: [x_filt ; n_filt] row-major, 2*4096*16000 floats.
//
// R2: ping-pong register buffers with STATIC indexing (R1's buf[cur][j]
// dynamic index demoted the prefetch buffer to local memory, killing MLP).

static constexpr int T_LEN  = 16000;
static constexpr int B_ROWS = 4096;
static constexpr int NF4    = T_LEN / 4;    // 4000 float4 per row
static constexpr int BATCH  = 16;           // float4 per register batch (64 floats)
static constexpr int NBATCH = NF4 / BATCH;  // 250 (even)

struct FState {
    float m0, m1, p0, p1;     // DF2T states: HP stage, random stage
    float a0, a1, b0, b1;     // random-stage coeffs
};

__device__ __forceinline__
void process_batch(const float4 (&buf)[BATCH], float4* __restrict__ dst, FState& s)
{
    const float A0 = -1.99599f;
    const float A1 =  0.996f;
    #pragma unroll
    for (int j = 0; j < BATCH; j++) {
        float4 v = buf[j];
        float xs[4] = {v.x, v.y, v.z, v.w};
        float ys[4];
        #pragma unroll
        for (int k = 0; k < 4; k++) {
            const float xv = xs[k];
            // Stage 1 (high-pass): y1 = x + m0
            const float y1 = xv + s.m0;
            s.m0 = fmaf(-A0, y1, fmaf(-2.0f, xv, s.m1));
            s.m1 = fmaf(-A1, y1, xv);
            // Stage 2 (random coeffs): y2 = y1 + p0
            const float y2 = y1 + s.p0;
            s.p0 = fmaf(-s.a0, y2, fmaf(s.b0, y1, s.p1));
            s.p1 = fmaf(-s.a1, y2, s.b1 * y1);
            ys[k] = y2;
        }
        dst[j] = make_float4(ys[0], ys[1], ys[2], ys[3]);
    }
}

__global__ __launch_bounds__(32, 1)
void biquad_cascade_kernel(const float* __restrict__ x,
                           const float* __restrict__ n,
                           const float* __restrict__ a_x,
                           const float* __restrict__ b_x,
                           const float* __restrict__ a_n,
                           const float* __restrict__ b_n,
                           float* __restrict__ out)
{
    const int r = blockIdx.x * 32 + threadIdx.x;   // 0..8191

    const float* in;
    FState s;
    s.m0 = 0.f; s.m1 = 0.f; s.p0 = 0.f; s.p1 = 0.f;
    if (r < B_ROWS) {
        in = x + (size_t)r * T_LEN;
        s.a0 = a_x[0]; s.a1 = a_x[1]; s.b0 = b_x[0]; s.b1 = b_x[1];
    } else {
        in = n + (size_t)(r - B_ROWS) * T_LEN;
        s.a0 = a_n[0]; s.a1 = a_n[1]; s.b0 = b_n[0]; s.b1 = b_n[1];
    }
    float* o = out + (size_t)r * T_LEN;

    const float4* in4 = (const float4*)in;
    float4*       o4  = (float4*)o;

    // Statically-indexed ping-pong buffers; 16 back-to-back LDG.128 per
    // prefetch gives real per-thread MLP=16 (256B in flight).
    float4 bufA[BATCH], bufB[BATCH];

    #pragma unroll
    for (int j = 0; j < BATCH; j++) bufA[j] = in4[j];

    for (int bi = 0; bi < NBATCH; bi += 2) {
        // Prefetch batch bi+1 into B (bi+1 <= 249 always valid).
        {
            const float4* src = in4 + (size_t)(bi + 1) * BATCH;
            #pragma unroll
            for (int j = 0; j < BATCH; j++) bufB[j] = src[j];
        }
        process_batch(bufA, o4 + (size_t)bi * BATCH, s);

        // Prefetch batch bi+2 into A.
        if (bi + 2 < NBATCH) {
            const float4* src = in4 + (size_t)(bi + 2) * BATCH;
            #pragma unroll
            for (int j = 0; j < BATCH; j++) bufA[j] = src[j];
        }
        process_batch(bufB, o4 + (size_t)(bi + 1) * BATCH, s);
    }
}

extern "C" void kernel_launch(void* const* d_in, const int* in_sizes, int n_in,
                              void* d_out, int out_size)
{
    const float* x   = (const float*)d_in[0];
    const float* n   = (const float*)d_in[1];
    const float* a_x = (const float*)d_in[2];
    const float* b_x = (const float*)d_in[3];
    const float* a_n = (const float*)d_in[4];
    const float* b_n = (const float*)d_in[5];
    float* out = (float*)d_out;

    biquad_cascade_kernel<<<(2 * B_ROWS) / 32, 32>>>(x, n, a_x, b_x, a_n, b_n, out);
}

// round 3
// speedup vs baseline: 1.3923x; 1.0521x over previous
#include <cuda_runtime.h>

// FilterTransform: two cascaded DF2T biquads over time for x[4096,16000] and
// n[4096,16000]. Stage 1 fixed high-pass (b=-2,1 / a=-1.99599,0.996),
// stage 2 uses scalar coeffs b_*[0], b_*[1] / a_*[0], a_*[1].
// Output: [x_filt ; n_filt] row-major.
//
// R3: 4-stage statically-indexed register pipeline (prefetch distance 3,
// 128B batches) to keep ~384B/thread continuously in flight. R2's depth-1
// pipeline averaged only ~60B/thread outstanding -> 2.36 TB/s ceiling.

static constexpr int T_LEN  = 16000;
static constexpr int B_ROWS = 4096;
static constexpr int NF4    = T_LEN / 4;    // 4000 float4 per row
static constexpr int BATCH  = 8;            // float4 per pipeline stage (32 floats)
static constexpr int NBATCH = NF4 / BATCH;  // 500 (divisible by 4)

struct FState {
    float m0, m1, p0, p1;     // DF2T states: HP stage, random stage
    float a0, a1, b0, b1;     // random-stage coeffs
};

__device__ __forceinline__
void prefetch(const float4* __restrict__ in4, int bi, float4 (&buf)[BATCH])
{
    if (bi < NBATCH) {
        const float4* src = in4 + (size_t)bi * BATCH;
        #pragma unroll
        for (int j = 0; j < BATCH; j++) buf[j] = src[j];
    }
}

__device__ __forceinline__
void process_batch(const float4 (&buf)[BATCH], float4* __restrict__ dst, FState& s)
{
    const float A0 = -1.99599f;
    const float A1 =  0.996f;
    #pragma unroll
    for (int j = 0; j < BATCH; j++) {
        float4 v = buf[j];
        float xs[4] = {v.x, v.y, v.z, v.w};
        float ys[4];
        #pragma unroll
        for (int k = 0; k < 4; k++) {
            const float xv = xs[k];
            // Stage 1 (high-pass): y1 = x + m0
            const float y1 = xv + s.m0;
            s.m0 = fmaf(-A0, y1, fmaf(-2.0f, xv, s.m1));
            s.m1 = fmaf(-A1, y1, xv);
            // Stage 2 (random coeffs): y2 = y1 + p0
            const float y2 = y1 + s.p0;
            s.p0 = fmaf(-s.a0, y2, fmaf(s.b0, y1, s.p1));
            s.p1 = fmaf(-s.a1, y2, s.b1 * y1);
            ys[k] = y2;
        }
        dst[j] = make_float4(ys[0], ys[1], ys[2], ys[3]);
    }
}

__global__ __launch_bounds__(32, 1)
void biquad_cascade_kernel(const float* __restrict__ x,
                           const float* __restrict__ n,
                           const float* __restrict__ a_x,
                           const float* __restrict__ b_x,
                           const float* __restrict__ a_n,
                           const float* __restrict__ b_n,
                           float* __restrict__ out)
{
    const int r = blockIdx.x * 32 + threadIdx.x;   // 0..8191

    const float* in;
    FState s;
    s.m0 = 0.f; s.m1 = 0.f; s.p0 = 0.f; s.p1 = 0.f;
    if (r < B_ROWS) {
        in = x + (size_t)r * T_LEN;
        s.a0 = a_x[0]; s.a1 = a_x[1]; s.b0 = b_x[0]; s.b1 = b_x[1];
    } else {
        in = n + (size_t)(r - B_ROWS) * T_LEN;
        s.a0 = a_n[0]; s.a1 = a_n[1]; s.b0 = b_n[0]; s.b1 = b_n[1];
    }
    float* o = out + (size_t)r * T_LEN;

    const float4* in4 = (const float4*)in;
    float4*       o4  = (float4*)o;

    // 4 statically-named pipeline buffers, prefetch distance 3.
    float4 buf0[BATCH], buf1[BATCH], buf2[BATCH], buf3[BATCH];

    prefetch(in4, 0, buf0);
    prefetch(in4, 1, buf1);
    prefetch(in4, 2, buf2);

    for (int g = 0; g < NBATCH; g += 4) {
        prefetch(in4, g + 3, buf3);
        process_batch(buf0, o4 + (size_t)(g + 0) * BATCH, s);

        prefetch(in4, g + 4, buf0);
        process_batch(buf1, o4 + (size_t)(g + 1) * BATCH, s);

        prefetch(in4, g + 5, buf1);
        process_batch(buf2, o4 + (size_t)(g + 2) * BATCH, s);

        prefetch(in4, g + 6, buf2);
        process_batch(buf3, o4 + (size_t)(g + 3) * BATCH, s);
    }
}

extern "C" void kernel_launch(void* const* d_in, const int* in_sizes, int n_in,
                              void* d_out, int out_size)
{
    const float* x   = (const float*)d_in[0];
    const float* n   = (const float*)d_in[1];
    const float* a_x = (const float*)d_in[2];
    const float* b_x = (const float*)d_in[3];
    const float* a_n = (const float*)d_in[4];
    const float* b_n = (const float*)d_in[5];
    float* out = (float*)d_out;

    biquad_cascade_kernel<<<(2 * B_ROWS) / 32, 32>>>(x, n, a_x, b_x, a_n, b_n, out);
}

// round 4
// speedup vs baseline: 2.7406x; 1.9684x over previous
#include <cuda_runtime.h>
#include <cstdint>

// FilterTransform: two cascaded DF2T biquads over time for x[4096,16000] and
// n[4096,16000]. Output: [x_filt ; n_filt] row-major.
//
// R4: coalesced access via smem tile staging. R1-R3 had each warp lane on a
// different row (64KB apart) -> 32 L1 wavefronts per LDG/STG.128, a ~230us
// L1-throughput floor. Now the warp cooperatively loads/stores 32-row x 512B
// tiles (contiguous 512B per instruction) with cp.async double buffering;
// each thread runs its serial IIR chain out of smem.

static constexpr int T_LEN  = 16000;
static constexpr int B_ROWS = 4096;
static constexpr int NF4    = T_LEN / 4;   // 4000 float4 per row
static constexpr int SEG    = 32;          // float4 per row per tile (512B)
static constexpr int NTILES = NF4 / SEG;   // 125
static constexpr int ROWS   = 32;          // rows per block (= warp size)
static constexpr int PAD    = 1;           // float4 padding per smem row

struct FState {
    float m0, m1, p0, p1;
    float a0, a1, b0, b1;
};

__device__ __forceinline__ void cp_async16(uint32_t saddr, const void* gptr) {
    asm volatile("cp.async.cg.shared.global [%0], [%1], 16;"
                 :: "r"(saddr), "l"(gptr) : "memory");
}
__device__ __forceinline__ void cp_commit() {
    asm volatile("cp.async.commit_group;" ::: "memory");
}
__device__ __forceinline__ void cp_wait1() {
    asm volatile("cp.async.wait_group 1;" ::: "memory");
}

__global__ __launch_bounds__(32)
void biquad_cascade_kernel(const float* __restrict__ x,
                           const float* __restrict__ n,
                           const float* __restrict__ a_x,
                           const float* __restrict__ b_x,
                           const float* __restrict__ a_n,
                           const float* __restrict__ b_n,
                           float* __restrict__ out)
{
    // tile[buf][row][seg] — PAD keeps LDS/STS conflict-free per 8-lane phase.
    __shared__ float4 tile[2][ROWS][SEG + PAD];

    const int lane    = threadIdx.x;            // 0..31
    const int rowbase = blockIdx.x * ROWS;      // multiple of 32; block entirely
                                                // inside x-half or n-half (4096%32==0)
    const bool is_x = (rowbase < B_ROWS);

    const float* inbase = is_x ? (x + (size_t)rowbase * T_LEN)
                               : (n + (size_t)(rowbase - B_ROWS) * T_LEN);
    float* outbase = out + (size_t)rowbase * T_LEN;

    FState s;
    s.m0 = 0.f; s.m1 = 0.f; s.p0 = 0.f; s.p1 = 0.f;
    if (is_x) { s.a0 = a_x[0]; s.a1 = a_x[1]; s.b0 = b_x[0]; s.b1 = b_x[1]; }
    else      { s.a0 = a_n[0]; s.a1 = a_n[1]; s.b0 = b_n[0]; s.b1 = b_n[1]; }

    const float A0 = -1.99599f;
    const float A1 =  0.996f;

    // ---- tile load: 32 cp.async, each 512B contiguous of one row ----
    auto issue_tile = [&](int g, int buf) {
        const float* src = inbase + (size_t)g * (SEG * 4) + lane * 4;
        #pragma unroll
        for (int i = 0; i < ROWS; i++) {
            uint32_t saddr = (uint32_t)__cvta_generic_to_shared(&tile[buf][i][lane]);
            cp_async16(saddr, src + (size_t)i * T_LEN);
        }
    };

    issue_tile(0, 0); cp_commit();
    issue_tile(1, 1); cp_commit();

    for (int g = 0; g < NTILES; g++) {
        const int buf = g & 1;

        cp_wait1();            // tile g landed (<=1 group pending: tile g+1)
        __syncwarp();

        // ---- compute: thread `lane` filters its row's 128 samples in-place ----
        {
            float4* myrow = &tile[buf][lane][0];
            #pragma unroll 8
            for (int j = 0; j < SEG; j++) {
                float4 v = myrow[j];
                float xs[4] = {v.x, v.y, v.z, v.w};
                float ys[4];
                #pragma unroll
                for (int k = 0; k < 4; k++) {
                    const float xv = xs[k];
                    const float y1 = xv + s.m0;                       // HP stage
                    s.m0 = fmaf(-A0, y1, fmaf(-2.0f, xv, s.m1));
                    s.m1 = fmaf(-A1, y1, xv);
                    const float y2 = y1 + s.p0;                       // random stage
                    s.p0 = fmaf(-s.a0, y2, fmaf(s.b0, y1, s.p1));
                    s.p1 = fmaf(-s.a1, y2, s.b1 * y1);
                    ys[k] = y2;
                }
                myrow[j] = make_float4(ys[0], ys[1], ys[2], ys[3]);
            }
        }
        __syncwarp();

        // ---- store: coalesced 512B STG.128 per row ----
        {
            float* dst = outbase + (size_t)g * (SEG * 4) + lane * 4;
            #pragma unroll
            for (int i = 0; i < ROWS; i++) {
                float4 v = tile[buf][i][lane];
                *(float4*)(dst + (size_t)i * T_LEN) = v;
            }
        }

        // ---- prefetch tile g+2 into this buffer (reads above are done) ----
        if (g + 2 < NTILES) issue_tile(g + 2, buf);
        cp_commit();           // empty group near the end keeps wait_group 1 exact
    }
}

extern "C" void kernel_launch(void* const* d_in, const int* in_sizes, int n_in,
                              void* d_out, int out_size)
{
    const float* x   = (const float*)d_in[0];
    const float* n   = (const float*)d_in[1];
    const float* a_x = (const float*)d_in[2];
    const float* b_x = (const float*)d_in[3];
    const float* a_n = (const float*)d_in[4];
    const float* b_n = (const float*)d_in[5];
    float* out = (float*)d_out;

    biquad_cascade_kernel<<<(2 * B_ROWS) / ROWS, 32>>>(x, n, a_x, b_x, a_n, b_n, out);
}

// round 5
// speedup vs baseline: 2.7938x; 1.0194x over previous
#include <cuda_runtime.h>
#include <cstdint>

// FilterTransform: cascaded biquads (fixed HP + random coeffs) over time,
// x[4096,16000] and n[4096,16000] -> out [8192,16000].
//
// R5: (1) cascade Direct-Form-I with compile-time HP coefficients so ptxas
// emits FFMA-imm (rt_SMSP=1) for stage 1: 13 fma-pipe cyc/sample vs 18 for
// the all-register DF2T (fma pipe rt=2 was R4's real binder).
// (2) 28 rows/warp (294 blocks) for near-perfect SM load balance.

static constexpr int T_LEN   = 16000;
static constexpr int HALF    = 4096;
static constexpr int SEG     = 32;           // float4 per row per tile (512B)
static constexpr int NTILES  = (T_LEN / 4) / SEG;  // 125
static constexpr int ROWS    = 28;           // rows per block (nominal)
static constexpr int XBLOCKS = (HALF + ROWS - 1) / ROWS;  // 147 (last = 8 rows)
static constexpr int PAD     = 1;            // +1 float4 -> 528B row stride (conflict-free)

__device__ __forceinline__ void cp_async16(uint32_t saddr, const void* gptr) {
    asm volatile("cp.async.cg.shared.global [%0], [%1], 16;"
                 :: "r"(saddr), "l"(gptr) : "memory");
}
__device__ __forceinline__ void cp_commit() {
    asm volatile("cp.async.commit_group;" ::: "memory");
}
__device__ __forceinline__ void cp_wait1() {
    asm volatile("cp.async.wait_group 1;" ::: "memory");
}

__global__ __launch_bounds__(32)
void biquad_cascade_kernel(const float* __restrict__ x,
                           const float* __restrict__ n,
                           const float* __restrict__ a_x,
                           const float* __restrict__ b_x,
                           const float* __restrict__ a_n,
                           const float* __restrict__ b_n,
                           float* __restrict__ out)
{
    __shared__ float4 tile[2][ROWS][SEG + PAD];

    const int lane = threadIdx.x;
    const bool is_x = (blockIdx.x < XBLOCKS);
    const int bi = is_x ? blockIdx.x : blockIdx.x - XBLOCKS;
    const int rowbase = bi * ROWS;
    const int nrows = (HALF - rowbase) < ROWS ? (HALF - rowbase) : ROWS;

    const float* inbase = is_x ? (x + (size_t)rowbase * T_LEN)
                               : (n + (size_t)rowbase * T_LEN);
    float* outbase = out + (size_t)(is_x ? rowbase : rowbase + HALF) * T_LEN;

    float a0, a1, b0, b1;
    if (is_x) { a0 = a_x[0]; a1 = a_x[1]; b0 = b_x[0]; b1 = b_x[1]; }
    else      { a0 = a_n[0]; a1 = a_n[1]; b0 = b_n[0]; b1 = b_n[1]; }
    const float na0 = -a0, na1 = -a1;

    // DF-I histories: input (x1,x2), HP output u (u1,u2), final output v (v1,v2)
    float x1 = 0.f, x2 = 0.f, u1 = 0.f, u2 = 0.f, v1 = 0.f, v2 = 0.f;

    auto issue_tile = [&](int g, int buf) {
        const float* src = inbase + (size_t)g * (SEG * 4) + lane * 4;
        for (int i = 0; i < nrows; i++) {
            uint32_t saddr = (uint32_t)__cvta_generic_to_shared(&tile[buf][i][lane]);
            cp_async16(saddr, src + (size_t)i * T_LEN);
        }
    };

    issue_tile(0, 0); cp_commit();
    issue_tile(1, 1); cp_commit();

    const bool active = (lane < nrows);

    for (int g = 0; g < NTILES; g++) {
        const int buf = g & 1;

        cp_wait1();          // tile g landed (<=1 group pending: tile g+1)
        __syncwarp();

        if (active) {
            float4* myrow = &tile[buf][lane][0];
            #pragma unroll 8
            for (int j = 0; j < SEG; j++) {
                float4 vin = myrow[j];
                float xs[4] = {vin.x, vin.y, vin.z, vin.w};
                float ys[4];
                #pragma unroll
                for (int k = 0; k < 4; k++) {
                    const float xv = xs[k];
                    // Stage 1 (HP, DF-I, compile-time coeffs -> FFMA-imm rt1):
                    // u = xv - 2*x1 + x2 + 1.99599*u1 - 0.996*u2
                    float t = fmaf(-2.0f, x1, xv);         // imm
                    t = t + x2;                            // FADD
                    t = fmaf(-0.996f, u2, t);              // imm
                    const float u = fmaf(1.99599f, u1, t); // imm (u1 last: 4-cyc chain)
                    // Stage 2 (runtime coeffs, DF-I):
                    // v = u + b0*u1 + b1*u2 - a0*v1 - a1*v2   (u1/u2 = previous u's)
                    float s = fmaf(b0, u1, u);
                    s = fmaf(b1, u2, s);
                    s = fmaf(na1, v2, s);
                    const float v = fmaf(na0, v1, s);      // v1 last: 4-cyc chain
                    x2 = x1; x1 = xv;
                    u2 = u1; u1 = u;
                    v2 = v1; v1 = v;
                    ys[k] = v;
                }
                myrow[j] = make_float4(ys[0], ys[1], ys[2], ys[3]);
            }
        }
        __syncwarp();

        // Coalesced store: 512B STG.128 per row.
        {
            float* dst = outbase + (size_t)g * (SEG * 4) + lane * 4;
            for (int i = 0; i < nrows; i++) {
                float4 v = tile[buf][i][lane];
                *(float4*)(dst + (size_t)i * T_LEN) = v;
            }
        }

        if (g + 2 < NTILES) issue_tile(g + 2, buf);
        cp_commit();         // keeps wait_group 1 bookkeeping exact near the end
    }
}

extern "C" void kernel_launch(void* const* d_in, const int* in_sizes, int n_in,
                              void* d_out, int out_size)
{
    const float* x   = (const float*)d_in[0];
    const float* n   = (const float*)d_in[1];
    const float* a_x = (const float*)d_in[2];
    const float* b_x = (const float*)d_in[3];
    const float* a_n = (const float*)d_in[4];
    const float* b_n = (const float*)d_in[5];
    float* out = (float*)d_out;

    biquad_cascade_kernel<<<2 * XBLOCKS, 32>>>(x, n, a_x, b_x, a_n, b_n, out);
}